// round 7
// baseline (speedup 1.0000x reference)
#include <cuda_runtime.h>

// Retina glimpse: x [B=16384, C=3, 32, 32] f32, l [B,2] f32 in [-1,1].
// Outputs concatenated into d_out:
//   full  [B,3,32,32] : x masked to the valid part of the 16x16 window, else 0
//   patch [B,3,16,16] : gathered window, 0 where out of [0,32) bounds
//
// This round: 2 samples per CTA, instruction streams statically interleaved
// (all loads -> all zero stores -> all dependent stores -> patches) to double
// per-warp memory-level parallelism without shrinking the grid much.

#define BB 16384
#define CC 3
#define HH 32
#define GG 16
#define FULL_PER_B (CC*HH*HH)   // 3072 floats
#define PATCH_PER_B (CC*GG*GG)  // 768 floats
#define SPB 2
#define NBLK (BB / SPB)         // 8192 CTAs

__global__ __launch_bounds__(256) void retina_kernel(
    const float* __restrict__ x,
    const float* __restrict__ l,
    float* __restrict__ full,
    float* __restrict__ patch)
{
    const int b0 = blockIdx.x * SPB;
    const int tid = threadIdx.x;
    const float4 z4 = make_float4(0.f, 0.f, 0.f, 0.f);

    // ---- geometry for both samples ----
    int rsA[SPB], csA[SPB];
    #pragma unroll
    for (int s = 0; s < SPB; ++s) {
        float l0 = fminf(fmaxf(__ldg(&l[2 * (b0 + s) + 0]), -1.0f), 1.0f);
        float l1 = fminf(fmaxf(__ldg(&l[2 * (b0 + s) + 1]), -1.0f), 1.0f);
        rsA[s] = (int)(0.5f * ((l0 + 1.0f) * 32.0f)) - GG / 2;  // [-8,24]
        csA[s] = (int)(0.5f * ((l1 + 1.0f) * 32.0f)) - GG / 2;
    }

    // Per-thread quad geometry: 3 tasks per sample, 6 total.
    // Task layout within a sample: v = it*256 + tid in [0,768).
    int  w0a[3];
    int  off[3];                 // element offset of the quad within a sample
    #pragma unroll
    for (int it = 0; it < 3; ++it) {
        int v = it * 256 + tid;
        int ch  = v >> 8;
        int rem = v & 255;
        int h   = rem >> 3;
        w0a[it] = (rem & 7) << 2;
        off[it] = (ch << 10) + (h << 5) + w0a[it];
    }

    bool ov[SPB][3];
    #pragma unroll
    for (int s = 0; s < SPB; ++s) {
        #pragma unroll
        for (int it = 0; it < 3; ++it) {
            int v = it * 256 + tid;
            int h = (v & 255) >> 3;
            ov[s][it] = (h >= rsA[s]) && (h < rsA[s] + GG) &&
                        (w0a[it] + 3 >= csA[s]) && (w0a[it] <= csA[s] + GG - 1);
        }
    }

    // ---- Group 1: issue ALL window loads (both samples) back-to-back ----
    float4 xv[SPB][3];
    #pragma unroll
    for (int s = 0; s < SPB; ++s) {
        const float* xb = x + (size_t)(b0 + s) * FULL_PER_B;
        #pragma unroll
        for (int it = 0; it < 3; ++it) {
            xv[s][it] = z4;
            if (ov[s][it])
                xv[s][it] = *(const float4*)(xb + off[it]);
        }
    }

    // ---- Group 2: independent zero stores (both samples, no SB waits) ----
    #pragma unroll
    for (int s = 0; s < SPB; ++s) {
        float* fb = full + (size_t)(b0 + s) * FULL_PER_B;
        #pragma unroll
        for (int it = 0; it < 3; ++it) {
            int v = it * 256 + tid;
            if (!ov[s][it])
                __stcs((float4*)(fb + ((size_t)v << 2)), z4);
        }
    }

    // ---- Group 3: dependent window stores (both samples) ----
    #pragma unroll
    for (int s = 0; s < SPB; ++s) {
        float* fb = full + (size_t)(b0 + s) * FULL_PER_B;
        int cs = csA[s];
        #pragma unroll
        for (int it = 0; it < 3; ++it) {
            if (ov[s][it]) {
                int v = it * 256 + tid;
                int w0 = w0a[it];
                float4 out;
                out.x = (w0 + 0 >= cs && w0 + 0 < cs + GG) ? xv[s][it].x : 0.f;
                out.y = (w0 + 1 >= cs && w0 + 1 < cs + GG) ? xv[s][it].y : 0.f;
                out.z = (w0 + 2 >= cs && w0 + 2 < cs + GG) ? xv[s][it].z : 0.f;
                out.w = (w0 + 3 >= cs && w0 + 3 < cs + GG) ? xv[s][it].w : 0.f;
                __stcs((float4*)(fb + ((size_t)v << 2)), out);
            }
        }
    }

    // ---- Patch phase: 2 x 192 float4 tasks over 256 threads ----
    // Task t in [0,384): s = t / 192, e4 = t % 192. Gathers mostly L1-hit.
    #pragma unroll
    for (int t = tid; t < SPB * 192; t += 256) {
        int s   = t / 192;
        int e4  = t % 192;
        int ch  = e4 >> 6;
        int rem = e4 & 63;
        int i   = rem >> 2;
        int j0  = (rem & 3) << 2;
        int row = rsA[s] + i;
        float4 out = z4;
        if (row >= 0 && row < HH) {
            const float* xr = x + (size_t)(b0 + s) * FULL_PER_B + (ch << 10) + (row << 5);
            int c0 = csA[s] + j0;
            if (c0 + 0 >= 0 && c0 + 0 < HH) out.x = xr[c0 + 0];
            if (c0 + 1 >= 0 && c0 + 1 < HH) out.y = xr[c0 + 1];
            if (c0 + 2 >= 0 && c0 + 2 < HH) out.z = xr[c0 + 2];
            if (c0 + 3 >= 0 && c0 + 3 < HH) out.w = xr[c0 + 3];
        }
        float* pb = patch + (size_t)(b0 + s) * PATCH_PER_B;
        __stcs((float4*)(pb + ((size_t)e4 << 2)), out);
    }
}

extern "C" void kernel_launch(void* const* d_in, const int* in_sizes, int n_in,
                              void* d_out, int out_size)
{
    const float* x = (const float*)d_in[0];   // [16384,3,32,32]
    const float* l = (const float*)d_in[1];   // [16384,2]
    float* full  = (float*)d_out;
    float* patch = (float*)d_out + (size_t)BB * FULL_PER_B;
    retina_kernel<<<NBLK, 256>>>(x, l, full, patch);
}

// round 8
// speedup vs baseline: 1.0302x; 1.0302x over previous
#include <cuda_runtime.h>
#include <cstdint>

// Retina glimpse: x [B=16384, C=3, 32, 32] f32, l [B,2] f32 in [-1,1].
// Outputs concatenated into d_out:
//   full  [B,3,32,32] : x masked to the valid part of the 16x16 window, else 0
//   patch [B,3,16,16] : gathered window, 0 where out of [0,32) bounds
//
// This round: build full+patch images in SMEM, then emit each as ONE
// cp.async.bulk shared->global transfer (12KB + 3KB contiguous bursts).

#define BB 16384
#define CC 3
#define HH 32
#define GG 16
#define FULL_PER_B (CC*HH*HH)   // 3072 floats = 12288 B
#define PATCH_PER_B (CC*GG*GG)  // 768 floats  = 3072 B

__device__ __forceinline__ uint32_t smem_u32(const void* p) {
    uint32_t a;
    asm("{ .reg .u64 t; cvta.to.shared.u64 t, %1; cvt.u32.u64 %0, t; }"
        : "=r"(a) : "l"(p));
    return a;
}

__global__ __launch_bounds__(256) void retina_kernel(
    const float* __restrict__ x,
    const float* __restrict__ l,
    float* __restrict__ full,
    float* __restrict__ patch)
{
    const int b = blockIdx.x;
    const int tid = threadIdx.x;
    const float4 z4 = make_float4(0.f, 0.f, 0.f, 0.f);

    __shared__ __align__(16) float4 s_full[FULL_PER_B / 4];   // 12288 B
    __shared__ __align__(16) float4 s_patch[PATCH_PER_B / 4]; //  3072 B

    // Window corner (per-thread; l loads are same-line L1 broadcasts).
    float l0 = fminf(fmaxf(__ldg(&l[2 * b + 0]), -1.0f), 1.0f);
    float l1 = fminf(fmaxf(__ldg(&l[2 * b + 1]), -1.0f), 1.0f);
    const int rs = (int)(0.5f * ((l0 + 1.0f) * 32.0f)) - GG / 2;  // [-8,24]
    const int cs = (int)(0.5f * ((l1 + 1.0f) * 32.0f)) - GG / 2;

    const float* xb = x + (size_t)b * FULL_PER_B;

    // ---- Build full image in smem: 768 float4, 3 per thread ----
    // Batch the (predicated) loads, then the selects + STS.
    float4 xv[3];
    int  w0a[3];
    bool ov[3];
    #pragma unroll
    for (int it = 0; it < 3; ++it) {
        int v = it * 256 + tid;             // [0,768)
        int ch  = v >> 8;
        int rem = v & 255;
        int h   = rem >> 3;
        int w0  = (rem & 7) << 2;
        w0a[it] = w0;
        ov[it] = (h >= rs) && (h < rs + GG) &&
                 (w0 + 3 >= cs) && (w0 <= cs + GG - 1);
        xv[it] = z4;
        if (ov[it])
            xv[it] = *(const float4*)(xb + (ch << 10) + (h << 5) + w0);
    }
    #pragma unroll
    for (int it = 0; it < 3; ++it) {
        int v = it * 256 + tid;
        int w0 = w0a[it];
        float4 out = z4;
        if (ov[it]) {
            out.x = (w0 + 0 >= cs && w0 + 0 < cs + GG) ? xv[it].x : 0.f;
            out.y = (w0 + 1 >= cs && w0 + 1 < cs + GG) ? xv[it].y : 0.f;
            out.z = (w0 + 2 >= cs && w0 + 2 < cs + GG) ? xv[it].z : 0.f;
            out.w = (w0 + 3 >= cs && w0 + 3 < cs + GG) ? xv[it].w : 0.f;
        }
        s_full[v] = out;
    }
    __syncthreads();

    // ---- Build patch image from s_full (it already equals masked x) ----
    if (tid < 192) {
        int e4  = tid;                      // float4 index [0,192)
        int ch  = e4 >> 6;
        int rem = e4 & 63;
        int i   = rem >> 2;                 // patch row [0,16)
        int j0  = (rem & 3) << 2;           // first patch col
        int row = rs + i;
        float4 out = z4;
        if (row >= 0 && row < HH) {
            const float* sf = (const float*)s_full + (ch << 10) + (row << 5);
            int c0 = cs + j0;
            if (c0 + 0 >= 0 && c0 + 0 < HH) out.x = sf[c0 + 0];
            if (c0 + 1 >= 0 && c0 + 1 < HH) out.y = sf[c0 + 1];
            if (c0 + 2 >= 0 && c0 + 2 < HH) out.z = sf[c0 + 2];
            if (c0 + 3 >= 0 && c0 + 3 < HH) out.w = sf[c0 + 3];
        }
        s_patch[e4] = out;
    }
    __syncthreads();

    // ---- Emit both images as bulk shared->global bursts ----
    if (tid == 0) {
        asm volatile("fence.proxy.async.shared::cta;" ::: "memory");
        float* fb = full  + (size_t)b * FULL_PER_B;
        float* pb = patch + (size_t)b * PATCH_PER_B;
        uint32_t sf = smem_u32(s_full);
        uint32_t sp = smem_u32(s_patch);
        asm volatile(
            "cp.async.bulk.global.shared::cta.bulk_group [%0], [%1], %2;"
            :: "l"(fb), "r"(sf), "n"(FULL_PER_B * 4) : "memory");
        asm volatile(
            "cp.async.bulk.global.shared::cta.bulk_group [%0], [%1], %2;"
            :: "l"(pb), "r"(sp), "n"(PATCH_PER_B * 4) : "memory");
        asm volatile("cp.async.bulk.commit_group;" ::: "memory");
        // Wait only until the SMEM source has been read (safe CTA exit).
        asm volatile("cp.async.bulk.wait_group.read 0;" ::: "memory");
    }
}

extern "C" void kernel_launch(void* const* d_in, const int* in_sizes, int n_in,
                              void* d_out, int out_size)
{
    const float* x = (const float*)d_in[0];   // [16384,3,32,32]
    const float* l = (const float*)d_in[1];   // [16384,2]
    float* full  = (float*)d_out;
    float* patch = (float*)d_out + (size_t)BB * FULL_PER_B;
    retina_kernel<<<BB, 256>>>(x, l, full, patch);
}

// round 9
// speedup vs baseline: 1.0335x; 1.0032x over previous
#include <cuda_runtime.h>

// Retina glimpse: x [B=16384, C=3, 32, 32] f32, l [B,2] f32 in [-1,1].
// Outputs concatenated into d_out:
//   full  [B,3,32,32] : x masked to the valid part of the 16x16 window, else 0
//   patch [B,3,16,16] : gathered window, 0 where out of [0,32) bounds
//
// Final configuration: best-measured structure (one CTA per sample, batched
// float4 traffic). Ordering: geometry -> zero stores (no producers, drain
// straight into the write path) -> window loads -> dependent stores -> patch.
// Eight structural variants all converge at ~5.3-5.4 TB/s; that is the HBM
// ceiling for this read/write mix, so this kernel sits on the roofline.

#define BB 16384
#define CC 3
#define HH 32
#define GG 16
#define FULL_PER_B (CC*HH*HH)   // 3072 floats
#define PATCH_PER_B (CC*GG*GG)  // 768 floats

__global__ __launch_bounds__(256) void retina_kernel(
    const float* __restrict__ x,
    const float* __restrict__ l,
    float* __restrict__ full,
    float* __restrict__ patch)
{
    const int b = blockIdx.x;
    const int tid = threadIdx.x;
    const float4 z4 = make_float4(0.f, 0.f, 0.f, 0.f);

    // Window corner (per-thread; l loads are same-line L1 broadcasts).
    float l0 = fminf(fmaxf(__ldg(&l[2 * b + 0]), -1.0f), 1.0f);
    float l1 = fminf(fmaxf(__ldg(&l[2 * b + 1]), -1.0f), 1.0f);
    const int rs = (int)(0.5f * ((l0 + 1.0f) * 32.0f)) - GG / 2;  // [-8,24]
    const int cs = (int)(0.5f * ((l1 + 1.0f) * 32.0f)) - GG / 2;

    const float* xb = x + (size_t)b * FULL_PER_B;
    float* fb = full + (size_t)b * FULL_PER_B;

    // Per-thread quad geometry for the 3 full-phase tasks.
    int  w0a[3], offs[3];
    bool ov[3];
    #pragma unroll
    for (int it = 0; it < 3; ++it) {
        int v = it * 256 + tid;             // [0,768) float4 index
        int ch  = v >> 8;
        int rem = v & 255;
        int h   = rem >> 3;
        w0a[it] = (rem & 7) << 2;
        offs[it] = (ch << 10) + (h << 5) + w0a[it];
        ov[it] = (h >= rs) && (h < rs + GG) &&
                 (w0a[it] + 3 >= cs) && (w0a[it] <= cs + GG - 1);
    }

    // ---- Group 1: independent zero stores FIRST (no producers) ----
    #pragma unroll
    for (int it = 0; it < 3; ++it) {
        int v = it * 256 + tid;
        if (!ov[it])
            __stcs((float4*)(fb + ((size_t)v << 2)), z4);
    }

    // ---- Group 2: window loads, batched ----
    float4 xv[3];
    #pragma unroll
    for (int it = 0; it < 3; ++it) {
        xv[it] = z4;
        if (ov[it])
            xv[it] = *(const float4*)(xb + offs[it]);
    }

    // ---- Group 3: dependent window stores ----
    #pragma unroll
    for (int it = 0; it < 3; ++it) {
        if (ov[it]) {
            int v = it * 256 + tid;
            int w0 = w0a[it];
            float4 out;
            out.x = (w0 + 0 >= cs && w0 + 0 < cs + GG) ? xv[it].x : 0.f;
            out.y = (w0 + 1 >= cs && w0 + 1 < cs + GG) ? xv[it].y : 0.f;
            out.z = (w0 + 2 >= cs && w0 + 2 < cs + GG) ? xv[it].z : 0.f;
            out.w = (w0 + 3 >= cs && w0 + 3 < cs + GG) ? xv[it].w : 0.f;
            __stcs((float4*)(fb + ((size_t)v << 2)), out);
        }
    }

    // ---- Patch phase: 192 float4/sample, threads 0..191 (L1 re-hits) ----
    if (tid < 192) {
        float* pb = patch + (size_t)b * PATCH_PER_B;
        int e4  = tid;                      // float4 index [0,192)
        int ch  = e4 >> 6;
        int rem = e4 & 63;
        int i   = rem >> 2;                 // patch row [0,16)
        int j0  = (rem & 3) << 2;           // first patch col of this float4
        int row = rs + i;
        float4 out = z4;
        if (row >= 0 && row < HH) {
            const float* xr = xb + (ch << 10) + (row << 5);
            int c0 = cs + j0;
            if (c0 + 0 >= 0 && c0 + 0 < HH) out.x = xr[c0 + 0];
            if (c0 + 1 >= 0 && c0 + 1 < HH) out.y = xr[c0 + 1];
            if (c0 + 2 >= 0 && c0 + 2 < HH) out.z = xr[c0 + 2];
            if (c0 + 3 >= 0 && c0 + 3 < HH) out.w = xr[c0 + 3];
        }
        __stcs((float4*)(pb + ((size_t)e4 << 2)), out);
    }
}

extern "C" void kernel_launch(void* const* d_in, const int* in_sizes, int n_in,
                              void* d_out, int out_size)
{
    const float* x = (const float*)d_in[0];   // [16384,3,32,32]
    const float* l = (const float*)d_in[1];   // [16384,2]
    float* full  = (float*)d_out;
    float* patch = (float*)d_out + (size_t)BB * FULL_PER_B;
    retina_kernel<<<BB, 256>>>(x, l, full, patch);
}